// round 14
// baseline (speedup 1.0000x reference)
#include <cuda_runtime.h>
#include <cuda_bf16.h>
#include <cuda_fp16.h>

// Problem dims (fixed by setup_inputs)
#define Nn 16
#define Cc 4
#define Hh 256
#define Ww 256
#define HW  (Hh * Ww)       // 65536
#define CHW (Cc * HW)       // 262144
#define INFV 1.0e10f
#define NBLK 1024           // main-pass blocks (4 rows each)
// Padded f1 plane: 4 guard rows (INF) above and below the 256 real rows.
#define PROWS 264
#define PSTRIDE (PROWS * 256)   // 67584 half elements per (n,c) plane

// Scratch (device globals: no allocation allowed)
__device__ __half g_f1h[Nn * Cc * PSTRIDE];  // padded C-pass output
__device__ float2 g_part[NBLK];              // per-block (num, den) partials
__device__ unsigned int g_ctr;               // last-block counter (self-wrapping)

__device__ __forceinline__ __half2 U2H(unsigned int u) { return *reinterpret_cast<__half2*>(&u); }
__device__ __forceinline__ unsigned int H2U(__half2 h)  { return *reinterpret_cast<unsigned int*>(&h); }

// ---------------------------------------------------------------------------
// C pass: f1[c] = min_{c'} (c-c')^2 + (t[c']!=0 ? 0 : INF), half, padded rows.
// First 16384 threads also fill the 8 guard rows per plane with INF.
__global__ void k_cpass(const int* __restrict__ tgt) {
    int idx = blockIdx.x * blockDim.x + threadIdx.x;   // over N*H*W/8 = 131072
    const unsigned int INFW = 0x5BF85BF8u;             // half2(255,255)

    if (idx < 16384) {   // pad fill: 64 planes x 8 rows x 256 half / 8 per uint4
        int plane = idx >> 8;
        int r8    = (idx >> 5) & 7;
        int word8 = idx & 31;
        int row   = (r8 < 4) ? r8 : 256 + r8;
        *(uint4*)(g_f1h + plane * PSTRIDE + (row << 8) + (word8 << 3)) =
            make_uint4(INFW, INFW, INFW, INFW);
    }

    int n   = idx >> 13;
    int rem = idx & 8191;
    int hw  = rem << 3;
    int row = hw >> 8, col = hw & 255;
    int base = n * CHW + hw;

    int4 a0a = *(const int4*)(tgt + base          ), a0b = *(const int4*)(tgt + base           + 4);
    int4 a1a = *(const int4*)(tgt + base +     HW ), a1b = *(const int4*)(tgt + base +     HW  + 4);
    int4 a2a = *(const int4*)(tgt + base + 2 * HW ), a2b = *(const int4*)(tgt + base + 2 * HW  + 4);
    int4 a3a = *(const int4*)(tgt + base + 3 * HW ), a3b = *(const int4*)(tgt + base + 3 * HW  + 4);

    float f0[8], f1[8], f2[8], f3[8];
#pragma unroll
    for (int k = 0; k < 8; k++) {
        bool t0 = ((k < 4) ? (&a0a.x)[k] : (&a0b.x)[k - 4]) != 0;
        bool t1 = ((k < 4) ? (&a1a.x)[k] : (&a1b.x)[k - 4]) != 0;
        bool t2 = ((k < 4) ? (&a2a.x)[k] : (&a2b.x)[k - 4]) != 0;
        bool t3 = ((k < 4) ? (&a3a.x)[k] : (&a3b.x)[k - 4]) != 0;
        f0[k] = t0 ? 0.f : (t1 ? 1.f : (t2 ? 4.f : (t3 ? 9.f : 255.f)));
        f1[k] = t1 ? 0.f : ((t0 || t2) ? 1.f : (t3 ? 4.f : 255.f));
        f2[k] = t2 ? 0.f : ((t1 || t3) ? 1.f : (t0 ? 4.f : 255.f));
        f3[k] = t3 ? 0.f : (t2 ? 1.f : (t1 ? 4.f : (t0 ? 9.f : 255.f)));
    }
    int obase = (n * Cc) * PSTRIDE + ((row + 4) << 8) + col;
    uint4 o;
    o = make_uint4(H2U(__floats2half2_rn(f0[0], f0[1])), H2U(__floats2half2_rn(f0[2], f0[3])),
                   H2U(__floats2half2_rn(f0[4], f0[5])), H2U(__floats2half2_rn(f0[6], f0[7])));
    *(uint4*)(g_f1h + obase              ) = o;
    o = make_uint4(H2U(__floats2half2_rn(f1[0], f1[1])), H2U(__floats2half2_rn(f1[2], f1[3])),
                   H2U(__floats2half2_rn(f1[4], f1[5])), H2U(__floats2half2_rn(f1[6], f1[7])));
    *(uint4*)(g_f1h + obase +     PSTRIDE) = o;
    o = make_uint4(H2U(__floats2half2_rn(f2[0], f2[1])), H2U(__floats2half2_rn(f2[2], f2[3])),
                   H2U(__floats2half2_rn(f2[4], f2[5])), H2U(__floats2half2_rn(f2[6], f2[7])));
    *(uint4*)(g_f1h + obase + 2 * PSTRIDE) = o;
    o = make_uint4(H2U(__floats2half2_rn(f3[0], f3[1])), H2U(__floats2half2_rn(f3[2], f3[3])),
                   H2U(__floats2half2_rn(f3[4], f3[5])), H2U(__floats2half2_rn(f3[6], f3[7])));
    *(uint4*)(g_f1h + obase + 3 * PSTRIDE) = o;
}

// ---------------------------------------------------------------------------
__device__ __forceinline__ float f1_at(int n, int c, int h, int w) {
    float v = __half2float(g_f1h[(n * Cc + c) * PSTRIDE + ((h + 4) << 8) + w]);
    return (v >= 255.f) ? INFV : v;
}

// Exact H-direction transform at one (n,c,h,w): radius-2 window (exact when
// result <= 9: outside cost >= 9) + rare full column scan.
__device__ float exact_f2(int n, int c, int h, int w) {
    float m = INFV;
    int j0 = h - 2 < 0 ? 0 : h - 2;
    int j1 = h + 2 > 255 ? 255 : h + 2;
    for (int j = j0; j <= j1; j++) {
        float dj = (float)(j - h);
        m = fminf(m, fmaf(dj, dj, f1_at(n, c, j, w)));
    }
    if (m > 9.0f) {
        m = INFV;
        for (int j = 0; j < Hh; j++) {
            float dj = (float)(j - h);
            m = fminf(m, fmaf(dj, dj, f1_at(n, c, j, w)));
        }
    }
    return m;
}

// Cold: recompute one thread's whole (4-pixel x 4-class) contribution exactly.
__device__ __noinline__ void recompute_unit(int n, int h, int w0,
                                            const float* __restrict__ pred,
                                            float& num, float& den) {
    num = 0.f; den = 0.f;
    for (int k = 0; k < 4; k++) {
        int w = w0 + k;
        float d[4], e[4];
        for (int c = 0; c < 4; c++) {
            float m = INFV;
            int j0 = w - 2 < 0 ? 0 : w - 2;
            int j1 = w + 2 > 255 ? 255 : w + 2;
            for (int j = j0; j <= j1; j++) {
                float dj = (float)(j - w);
                m = fminf(m, fmaf(dj, dj, exact_f2(n, c, h, j)));
            }
            if (m > 9.0f) {
                m = INFV;
                for (int j = 0; j < Ww; j++) {
                    float dj = (float)(j - w);
                    m = fminf(m, fmaf(dj, dj, exact_f2(n, c, h, j)));
                }
            }
            d[c] = sqrtf(m);
            e[c] = __expf(pred[n * CHW + c * HW + (h << 8) + w]);
        }
        float es = e[0] + e[1] + e[2] + e[3];
        num += (e[0] * d[0] + e[1] * d[1] + e[2] * d[2] + e[3] * d[3]) / es;
        den += d[0] + d[1] + d[2] + d[3];
    }
}

__device__ __forceinline__ float fsqrt_approx(float x) {
    float r;
    asm("sqrt.approx.f32 %0, %1;" : "=f"(r) : "f"(x));
    return r;
}

// ---------------------------------------------------------------------------
// Main pass. Block = 4 consecutive (n,h) rows, 256 threads, SINGLE WAVE.
// RADIUS-2 windows everywhere: any result <= 9 is provably exact (outside
// cost >= 9); a >9 value at any pixel (P ~ 2^-76 per voxel) trips the cold
// exact recompute.
// P1: thread = (class, 4-px column); 8 unconditional LDG.64 from the padded
//     plane, register-rolled into 4 H-pass word-pairs (2 min-plus levels).
// P2: thread = (row, 4-px); W window via 3 PRMT half-shifts + softmax + reduce.
__global__ void __launch_bounds__(256, 8) k_main(const float* __restrict__ pred,
                                                 float* __restrict__ out) {
    __shared__ unsigned int s_f2[4][4][132];  // [class][row][2 + 128 + 2] half2 words
    __shared__ float rnum[8], rden[8];
    __shared__ bool  s_last;

    const __half2 C1 = __float2half2_rn(1.0f);
    const __half2 C4 = __float2half2_rn(4.0f);
    const unsigned int INFW = 0x5BF85BF8u;    // half2(255, 255)

    int tid = threadIdx.x;
    int n = blockIdx.x >> 6;
    int h0 = (blockIdx.x & 63) << 2;

    // s_f2 borders
    if (tid < 64) {
        int c = tid >> 4, r = (tid >> 2) & 3, b = tid & 3;
        s_f2[c][r][b < 2 ? b : 128 + b] = INFW;
    }

    // ---- P1: H-direction (radius 2, native half2 min-plus) ----
    {
        int c = tid >> 6, t = tid & 63;
        // row (h0-2+s) lives at padded row (h0+2+s)
        const __half* __restrict__ pc =
            g_f1h + (n * Cc + c) * PSTRIDE + ((h0 + 2) << 8) + (t << 2);
        uint2 v[8];
#pragma unroll
        for (int s = 0; s < 8; s++)
            v[s] = *(const uint2*)(pc + (s << 8));
#pragma unroll
        for (int r = 0; r < 4; r++) {
            __half2 aA = U2H(v[r + 2].x), aB = U2H(v[r + 2].y);
            aA = __hmin2(aA, __hadd2(__hmin2(U2H(v[r + 1].x), U2H(v[r + 3].x)), C1));
            aB = __hmin2(aB, __hadd2(__hmin2(U2H(v[r + 1].y), U2H(v[r + 3].y)), C1));
            aA = __hmin2(aA, __hadd2(__hmin2(U2H(v[r    ].x), U2H(v[r + 4].x)), C4));
            aB = __hmin2(aB, __hadd2(__hmin2(U2H(v[r    ].y), U2H(v[r + 4].y)), C4));
            *(uint2*)&s_f2[c][r][2 + 2 * t] = make_uint2(H2U(aA), H2U(aB));
        }
    }
    __syncthreads();

    // ---- P2: W-direction (radius 2) + softmax ----
    float num, den;
    {
        int row = tid >> 6, t = tid & 63;
        int h = h0 + row, w0 = t << 2;
        int pbase = n * CHW + (h << 8) + w0;

        float se[4]  = {0.f, 0.f, 0.f, 0.f};
        float sed[4] = {0.f, 0.f, 0.f, 0.f};
        den = 0.f;
        __half2 hmx = __float2half2_rn(0.0f);

#pragma unroll
        for (int c = 0; c < 4; c++) {
            const unsigned int* __restrict__ sb = s_f2[c][row];
            uint2 wa = *(const uint2*)(sb + 2 * t);      // words 2t-2 (m2), 2t-1 (m1)
            uint2 wb = *(const uint2*)(sb + 2 * t + 2);  // 2t (c0), 2t+1 (c1)
            uint2 wc = *(const uint2*)(sb + 2 * t + 4);  // 2t+2 (p1), 2t+3

            unsigned int m1 = wa.y, c0 = wb.x, c1 = wb.y, p1 = wc.x;
            unsigned int P0 = __byte_perm(m1, c0, 0x5432);  // (y-1, y0)
            unsigned int P1 = __byte_perm(c0, c1, 0x5432);  // (y1, y2)
            unsigned int P2 = __byte_perm(c1, p1, 0x5432);  // (y3, y4)

            __half2 aA = U2H(c0), aB = U2H(c1);
            aA = __hmin2(aA, __hadd2(__hmin2(U2H(P0), U2H(P1)), C1));
            aB = __hmin2(aB, __hadd2(__hmin2(U2H(P1), U2H(P2)), C1));
            aA = __hmin2(aA, __hadd2(__hmin2(U2H(m1), U2H(c1)), C4));
            aB = __hmin2(aB, __hadd2(__hmin2(U2H(c0), U2H(p1)), C4));
            hmx = __hmax2(hmx, __hmax2(aA, aB));

            float2 fA = __half22float2(aA), fB = __half22float2(aB);
            float d0 = fsqrt_approx(fA.x), d1 = fsqrt_approx(fA.y);
            float d2 = fsqrt_approx(fB.x), d3 = fsqrt_approx(fB.y);

            float4 x4 = *(const float4*)(pred + pbase + c * HW);
            float e0 = __expf(x4.x), e1 = __expf(x4.y), e2 = __expf(x4.z), e3 = __expf(x4.w);
            se[0]  += e0;      se[1]  += e1;      se[2]  += e2;      se[3]  += e3;
            sed[0] += e0 * d0; sed[1] += e1 * d1; sed[2] += e2 * d2; sed[3] += e3 * d3;
            den += (d0 + d1) + (d2 + d3);
        }

        num = __fdividef(sed[0], se[0]) + __fdividef(sed[1], se[1]) +
              __fdividef(sed[2], se[2]) + __fdividef(sed[3], se[3]);

        float chk = fmaxf(__half2float(__low2half(hmx)), __half2float(__high2half(hmx)));
        if (chk > 9.0f)      // astronomically cold: redo this unit exactly
            recompute_unit(n, h, w0, pred, num, den);
    }

    // ---- block reduce ----
#pragma unroll
    for (int o = 16; o; o >>= 1) {
        num += __shfl_xor_sync(0xFFFFFFFFu, num, o);
        den += __shfl_xor_sync(0xFFFFFFFFu, den, o);
    }
    int lane = tid & 31, wid = tid >> 5;
    if (lane == 0) { rnum[wid] = num; rden[wid] = den; }
    __syncthreads();
    if (wid == 0) {
        num = (lane < 8) ? rnum[lane] : 0.f;
        den = (lane < 8) ? rden[lane] : 0.f;
#pragma unroll
        for (int o = 4; o; o >>= 1) {
            num += __shfl_xor_sync(0xFFFFFFFFu, num, o);
            den += __shfl_xor_sync(0xFFFFFFFFu, den, o);
        }
        if (lane == 0) g_part[blockIdx.x] = make_float2(num, den);
    }

    // ---- last-block final reduction (self-resetting counter) ----
    __threadfence();
    if (threadIdx.x == 0) {
        unsigned int prevc = atomicInc(&g_ctr, NBLK - 1);  // wraps to 0 on last
        s_last = (prevc == (unsigned int)(NBLK - 1));
    }
    __syncthreads();
    if (!s_last) return;

    __shared__ double snum[8], sden[8];
    double dn = 0.0, dd = 0.0;
#pragma unroll
    for (int q = 0; q < NBLK / 256; q++) {
        float2 p = g_part[q * 256 + tid];
        dn += (double)p.x;
        dd += (double)p.y;
    }
#pragma unroll
    for (int o = 16; o; o >>= 1) {
        dn += __shfl_xor_sync(0xFFFFFFFFu, dn, o);
        dd += __shfl_xor_sync(0xFFFFFFFFu, dd, o);
    }
    if (lane == 0) { snum[wid] = dn; sden[wid] = dd; }
    __syncthreads();
    if (wid == 0) {
        dn = (lane < 8) ? snum[lane] : 0.0;
        dd = (lane < 8) ? sden[lane] : 0.0;
#pragma unroll
        for (int o = 4; o; o >>= 1) {
            dn += __shfl_xor_sync(0xFFFFFFFFu, dn, o);
            dd += __shfl_xor_sync(0xFFFFFFFFu, dd, o);
        }
        if (lane == 0) out[0] = (float)(dn / (dd + 1e-10));
    }
}

// ---------------------------------------------------------------------------
extern "C" void kernel_launch(void* const* d_in, const int* in_sizes, int n_in,
                              void* d_out, int out_size) {
    const float* pred = (const float*)d_in[0];
    const int*   tgt  = (const int*)d_in[1];
    float*       out  = (float*)d_out;

    k_cpass<<<(Nn * HW / 8) / 256, 256>>>(tgt);
    k_main<<<NBLK, 256>>>(pred, out);
}